// round 3
// baseline (speedup 1.0000x reference)
#include <cuda_runtime.h>

// Fused Swin-window MHSA, fp32.
// One CTA = one (batch, window). 256 threads.
// Pipeline per head: stage W_h in smem -> Q,K,V gemms -> scores(+bias) ->
// softmax -> AV -> accumulate O-projection into registers. Final store once.

#define TPB     256
#define DDIM    128      // per-head dim == model dim
#define HEADS   8
#define WINSZ   7
#define PTOK    49       // tokens per window
#define JPAD    64       // padded token dim
#define CW      112      // patch-grid width (448/4)
#define NPATCH  12544    // tokens per image
#define NWIN    256      // windows per image (16x16)

struct SmemLayout {
    float xs[DDIM * JPAD];      // x window, d-major, cols 49..63 zeroed
    float qs[DDIM * JPAD];      // q (later reused as attention-output oh)
    float ks[DDIM * JPAD];      // k
    float vt[PTOK * DDIM];      // v, token-major (transposed)
    float ws[64 * 64];          // attention scores / weights
    float As[DDIM * DDIM];      // staged weight block [row][k]
    float bias[176];            // per-head relative position bias (169 used)
    int   pidx[64];             // window token -> patch index
    unsigned char rel[64 * 64]; // relative-index table
};

__device__ __forceinline__ void copy_contig(float* dst, const float* __restrict__ src, int tid) {
    float4* d4 = reinterpret_cast<float4*>(dst);
    const float4* s4 = reinterpret_cast<const float4*>(src);
    #pragma unroll
    for (int it = 0; it < 16; ++it)
        d4[tid + it * TPB] = s4[tid + it * TPB];
}

__device__ __forceinline__ void copy_wo(float* dst, const float* __restrict__ Wo, int hh, int tid) {
    float4* d4 = reinterpret_cast<float4*>(dst);
    #pragma unroll
    for (int it = 0; it < 16; ++it) {
        int f4 = tid + it * TPB;
        int r  = f4 >> 5;        // 32 float4 per 128-float row
        int k4 = f4 & 31;
        d4[f4] = *reinterpret_cast<const float4*>(Wo + r * 1024 + hh * 128 + k4 * 4);
    }
}

// acc[4][8] += A[128x128 row-major] @ B[128xJPAD], rows r0..r0+3, cols j0..j0+7
__device__ __forceinline__ void gemm128(const float* __restrict__ A, const float* __restrict__ B,
                                        int r0, int j0, float acc[4][8]) {
    #pragma unroll 4
    for (int k = 0; k < 128; ++k) {
        float4 b0 = *reinterpret_cast<const float4*>(&B[k * JPAD + j0]);
        float4 b1 = *reinterpret_cast<const float4*>(&B[k * JPAD + j0 + 4]);
        float bb[8] = {b0.x, b0.y, b0.z, b0.w, b1.x, b1.y, b1.z, b1.w};
        float aa[4];
        #pragma unroll
        for (int rr = 0; rr < 4; ++rr) aa[rr] = A[(r0 + rr) * 128 + k];
        #pragma unroll
        for (int rr = 0; rr < 4; ++rr)
            #pragma unroll
            for (int cc = 0; cc < 8; ++cc)
                acc[rr][cc] = fmaf(aa[rr], bb[cc], acc[rr][cc]);
    }
}

__global__ __launch_bounds__(TPB, 1)
void win_msa_kernel(const float* __restrict__ x,
                    const float* __restrict__ Wq, const float* __restrict__ bq,
                    const float* __restrict__ Wk, const float* __restrict__ bk,
                    const float* __restrict__ Wv, const float* __restrict__ bv,
                    const float* __restrict__ Wo, const float* __restrict__ bo,
                    const float* __restrict__ pos,
                    float* __restrict__ out) {
    extern __shared__ float smem_raw[];
    SmemLayout& sm = *reinterpret_cast<SmemLayout*>(smem_raw);

    const int tid = threadIdx.x;
    const int blk = blockIdx.x;
    const int n  = blk >> 8;            // image
    const int w  = blk & 255;           // window
    const int wy = w >> 4, wx = w & 15;

    const int cg = tid & 7;             // col group (8 cols each)
    const int rg = tid >> 3;            // row group (4 rows each)
    const int r0 = rg * 4;
    const int j0 = cg * 8;

    // ---- static tables ----
    if (tid < 64) {
        int j  = tid;
        int pr = j / 7, pc = j % 7;
        sm.pidx[j] = (j < PTOK) ? ((wy * 7 + pr) * CW + wx * 7 + pc) : 0;
    }
    for (int f = tid; f < 64 * 64; f += TPB) {
        int i = f >> 6, j = f & 63;
        int v = 0;
        if (i < PTOK && j < PTOK) {
            int ri = i / 7, ci = i % 7, rj = j / 7, cj = j % 7;
            v = (ri - rj + 6) + (ci - cj + 6) * 13;
        }
        sm.rel[f] = (unsigned char)v;
    }
    __syncthreads();

    // ---- load x window (zero the padding columns) ----
    const float* xb = x + (size_t)n * DDIM * NPATCH;
    for (int f = tid; f < DDIM * JPAD; f += TPB) {
        int d = f >> 6, j = f & 63;
        sm.xs[f] = (j < PTOK) ? xb[d * NPATCH + sm.pidx[j]] : 0.f;
    }

    // ---- persistent output accumulator (init with bo) ----
    float oacc[4][8];
    #pragma unroll
    for (int rr = 0; rr < 4; ++rr) {
        float b = bo[r0 + rr];
        #pragma unroll
        for (int cc = 0; cc < 8; ++cc) oacc[rr][cc] = b;
    }

    const float scale = 0.088388347648318447f;  // 1/sqrt(128)

    for (int hh = 0; hh < HEADS; ++hh) {
        __syncthreads();  // protect As/qs(oh)/bias from previous iteration readers
        if (tid < 169) sm.bias[tid] = pos[tid * HEADS + hh];

        // ---- Q ----
        copy_contig(sm.As, Wq + hh * 128 * 128, tid);
        __syncthreads();
        {
            float acc[4][8] = {};
            gemm128(sm.As, sm.xs, r0, j0, acc);
            #pragma unroll
            for (int rr = 0; rr < 4; ++rr) {
                float b = bq[hh * 128 + r0 + rr];
                #pragma unroll
                for (int cc = 0; cc < 8; ++cc)
                    sm.qs[(r0 + rr) * JPAD + j0 + cc] = acc[rr][cc] + b;
            }
        }
        __syncthreads();

        // ---- K ----
        copy_contig(sm.As, Wk + hh * 128 * 128, tid);
        __syncthreads();
        {
            float acc[4][8] = {};
            gemm128(sm.As, sm.xs, r0, j0, acc);
            #pragma unroll
            for (int rr = 0; rr < 4; ++rr) {
                float b = bk[hh * 128 + r0 + rr];
                #pragma unroll
                for (int cc = 0; cc < 8; ++cc)
                    sm.ks[(r0 + rr) * JPAD + j0 + cc] = acc[rr][cc] + b;
            }
        }
        __syncthreads();

        // ---- V (stored transposed: token-major) ----
        copy_contig(sm.As, Wv + hh * 128 * 128, tid);
        __syncthreads();
        {
            float acc[4][8] = {};
            gemm128(sm.As, sm.xs, r0, j0, acc);
            #pragma unroll
            for (int cc = 0; cc < 8; ++cc) {
                int tok = j0 + cc;
                if (tok < PTOK) {
                    #pragma unroll
                    for (int rr = 0; rr < 4; ++rr)
                        sm.vt[tok * DDIM + r0 + rr] = acc[rr][cc] + bv[hh * 128 + r0 + rr];
                }
            }
        }
        __syncthreads();

        // ---- scores: S[i,j] = sum_d k[d,i] * q[d,j], 2x8 tile per thread ----
        {
            const int i0 = (tid >> 3) * 2;  // 0..62
            float acc[2][8] = {};
            #pragma unroll 4
            for (int d = 0; d < 128; ++d) {
                float a0 = sm.ks[d * JPAD + i0];
                float a1 = sm.ks[d * JPAD + i0 + 1];
                float4 b0 = *reinterpret_cast<const float4*>(&sm.qs[d * JPAD + j0]);
                float4 b1 = *reinterpret_cast<const float4*>(&sm.qs[d * JPAD + j0 + 4]);
                float bb[8] = {b0.x, b0.y, b0.z, b0.w, b1.x, b1.y, b1.z, b1.w};
                #pragma unroll
                for (int cc = 0; cc < 8; ++cc) {
                    acc[0][cc] = fmaf(a0, bb[cc], acc[0][cc]);
                    acc[1][cc] = fmaf(a1, bb[cc], acc[1][cc]);
                }
            }
            #pragma unroll
            for (int ii = 0; ii < 2; ++ii)
                #pragma unroll
                for (int cc = 0; cc < 8; ++cc) {
                    int i = i0 + ii, j = j0 + cc;
                    sm.ws[i * 64 + j] = acc[ii][cc] * scale + sm.bias[sm.rel[i * 64 + j]];
                }
        }
        __syncthreads();

        // ---- softmax over key index i (one thread per query column j) ----
        if (tid < PTOK) {
            const int j = tid;
            float m = sm.ws[j];
            for (int i = 1; i < PTOK; ++i) m = fmaxf(m, sm.ws[i * 64 + j]);
            float s = 0.f;
            for (int i = 0; i < PTOK; ++i) {
                float e = __expf(sm.ws[i * 64 + j] - m);
                sm.ws[i * 64 + j] = e;
                s += e;
            }
            float r = 1.f / s;
            for (int i = 0; i < PTOK; ++i) sm.ws[i * 64 + j] *= r;
        }
        __syncthreads();

        // ---- AV: oh[d,j] = sum_i v[d,i] * w[i,j]  (oh stored into qs buffer) ----
        {
            float acc[4][8] = {};
            #pragma unroll 7
            for (int i = 0; i < PTOK; ++i) {
                float4 a = *reinterpret_cast<const float4*>(&sm.vt[i * DDIM + r0]);
                float4 b0 = *reinterpret_cast<const float4*>(&sm.ws[i * 64 + j0]);
                float4 b1 = *reinterpret_cast<const float4*>(&sm.ws[i * 64 + j0 + 4]);
                float aa[4] = {a.x, a.y, a.z, a.w};
                float bb[8] = {b0.x, b0.y, b0.z, b0.w, b1.x, b1.y, b1.z, b1.w};
                #pragma unroll
                for (int rr = 0; rr < 4; ++rr)
                    #pragma unroll
                    for (int cc = 0; cc < 8; ++cc)
                        acc[rr][cc] = fmaf(aa[rr], bb[cc], acc[rr][cc]);
            }
            #pragma unroll
            for (int rr = 0; rr < 4; ++rr)
                #pragma unroll
                for (int cc = 0; cc < 8; ++cc)
                    sm.qs[(r0 + rr) * JPAD + j0 + cc] = acc[rr][cc];
        }
        __syncthreads();

        // ---- O projection: oacc += Wo[:, hh*128:+128] @ oh ----
        copy_wo(sm.As, Wo, hh, tid);
        __syncthreads();
        gemm128(sm.As, sm.qs, r0, j0, oacc);
        // loop-top __syncthreads() protects As/qs before next head overwrites
    }

    // ---- final store ----
    float* ob = out + (size_t)n * DDIM * NPATCH;
    #pragma unroll
    for (int cc = 0; cc < 8; ++cc) {
        int j = j0 + cc;
        if (j < PTOK) {
            int p = sm.pidx[j];
            #pragma unroll
            for (int rr = 0; rr < 4; ++rr)
                ob[(size_t)(r0 + rr) * NPATCH + p] = oacc[rr][cc];
        }
    }
}

extern "C" void kernel_launch(void* const* d_in, const int* in_sizes, int n_in,
                              void* d_out, int out_size) {
    (void)in_sizes; (void)n_in; (void)out_size;
    const float* x   = (const float*)d_in[0];
    const float* Wq  = (const float*)d_in[1];
    const float* bq  = (const float*)d_in[2];
    const float* Wk  = (const float*)d_in[3];
    const float* bk  = (const float*)d_in[4];
    const float* Wv  = (const float*)d_in[5];
    const float* bv  = (const float*)d_in[6];
    const float* Wo  = (const float*)d_in[7];
    const float* bo  = (const float*)d_in[8];
    const float* pos = (const float*)d_in[9];
    float* out = (float*)d_out;

    const int smem_bytes = (int)sizeof(SmemLayout);
    cudaFuncSetAttribute(win_msa_kernel,
                         cudaFuncAttributeMaxDynamicSharedMemorySize, smem_bytes);

    // 4 images * 256 windows = 1024 CTAs
    win_msa_kernel<<<1024, TPB, smem_bytes>>>(x, Wq, bq, Wk, bk, Wv, bv, Wo, bo, pos, out);
}